// round 7
// baseline (speedup 1.0000x reference)
#include <cuda_runtime.h>
#include <cuda_bf16.h>
#include <math.h>
#include <stdint.h>

// ---------------- dims ----------------
#define NPTS 131072
#define PTS  64             // points per block
#define TPB  128            // 4 warps, each owns 16 points x full N=128
#define NBLK (NPTS/PTS)     // 2048
#define HID  128
#define L1_KT 13            // K = 208 (194 real + bias row + pad)
#define L23_KT 8            // K = 128

// ---------------- A smem layout (bytes) ----------------
#define SA_STRIDE 432       // feature row stride: 216 bf16 (16B-aligned, ldsm conflict-free)
#define SA_HALF   27648     // 64*432, lo buffer offset
#define SM_B2 0             // b2: 128 f32
#define SM_B3 512           // b3: 128 f32
#define SM_A  1024
#define SM_TOTAL (SM_A + 2*SA_HALF)   // 56320

// weight fragment array (uint4 units): [layer][kt][nt 0..15][lane]
#define WF_L1 0
#define WF_L2 6656          // 13*512
#define WF_L3 10752
#define WF_TOTAL 14848

// ---------------- device scratch ----------------
__device__ float g_zt[16*64*64*64];          // z transposed (B,H,W,C)
__device__ uint4 g_wfrag[WF_TOTAL];          // MMA b-fragments {b0h,b1h,b0l,b1l}
__device__ float g_wh[HID*8];                // head weights [k][o]
__device__ float g_hb[8];                    // head biases

// ---------------- helpers ----------------
__device__ __forceinline__ uint32_t smem_u32(const void* p) {
    uint32_t a;
    asm("{ .reg .u64 t; cvta.to.shared.u64 t, %1; cvt.u32.u64 %0, t; }" : "=r"(a) : "l"(p));
    return a;
}
__device__ __forceinline__ void ldsm4(uint32_t* r, uint32_t a) {
    asm volatile("ldmatrix.sync.aligned.m8n8.x4.shared.b16 {%0,%1,%2,%3}, [%4];"
                 : "=r"(r[0]), "=r"(r[1]), "=r"(r[2]), "=r"(r[3]) : "r"(a));
}
__device__ __forceinline__ void mma_bf16(float* d, const uint32_t* a, uint32_t b0, uint32_t b1) {
    asm volatile("mma.sync.aligned.m16n8k16.row.col.f32.bf16.bf16.f32 "
                 "{%0,%1,%2,%3}, {%4,%5,%6,%7}, {%8,%9}, {%0,%1,%2,%3};"
                 : "+f"(d[0]), "+f"(d[1]), "+f"(d[2]), "+f"(d[3])
                 : "r"(a[0]), "r"(a[1]), "r"(a[2]), "r"(a[3]), "r"(b0), "r"(b1));
}
// fast tanh: 1 - 2/(exp(2x)+1); ~1e-6 abs err
__device__ __forceinline__ float ftanh(float x) {
    float e = __expf(2.f * x);
    float r;
    asm("rcp.approx.f32 %0, %1;" : "=f"(r) : "f"(e + 1.f));
    return fmaf(-2.f, r, 1.f);
}
// pack (a,b) fp32 pair -> hi bf16x2 word + lo (residual) bf16x2 word
__device__ __forceinline__ void split2(float a, float b, uint32_t& hi, uint32_t& lo) {
    __nv_bfloat16 ah = __float2bfloat16(a), bh = __float2bfloat16(b);
    __nv_bfloat16 al = __float2bfloat16(a - __bfloat162float(ah));
    __nv_bfloat16 bl = __float2bfloat16(b - __bfloat162float(bh));
    hi = (uint32_t)__bfloat16_as_ushort(ah) | ((uint32_t)__bfloat16_as_ushort(bh) << 16);
    lo = (uint32_t)__bfloat16_as_ushort(al) | ((uint32_t)__bfloat16_as_ushort(bl) << 16);
}
// fast sin/cos with explicit 2-step 2*pi range reduction (|x| up to ~1e3)
__device__ __forceinline__ void fsincos(float x, float& s, float& c) {
    float k = rintf(x * 0.15915494309189535f);      // 1/(2pi)
    float r = fmaf(-k, 6.2831855f, x);              // C1 = float(2pi)
    r = fmaf(-k, -1.7484555e-7f, r);                // C2 = 2pi - C1
    s = __sinf(r);
    c = __cosf(r);
}

// ---------------- prologue kernels ----------------
__global__ void __launch_bounds__(256) transpose_z_kernel(const float* __restrict__ z) {
    int i = blockIdx.x * 256 + threadIdx.x;
    int x = i & 63, y = (i >> 6) & 63, c = (i >> 12) & 63, b = i >> 18;
    g_zt[(((((b << 6) + y) << 6) + x) << 6) + c] = z[i];
}

// Pre-pack weights into MMA col-major b-fragment layout.
// lane l, n-tile nt, k-tile kt:  n = nt*8 + l/4,  k0 = kt*16 + (l%4)*2
__global__ void __launch_bounds__(256) prep_wfrag_kernel(
    const float* __restrict__ W1, const float* __restrict__ b1,
    const float* __restrict__ W2, const float* __restrict__ W3)
{
    int i = blockIdx.x * 256 + threadIdx.x;
    if (i >= WF_TOTAL) return;
    int layer, rem;
    const float* W;
    if (i < WF_L2)      { layer = 1; rem = i;          W = W1; }
    else if (i < WF_L3) { layer = 2; rem = i - WF_L2;  W = W2; }
    else                { layer = 3; rem = i - WF_L3;  W = W3; }
    int lane = rem & 31, nt = (rem >> 5) & 15, kt = rem >> 9;
    int n  = nt * 8 + (lane >> 2);
    int k0 = kt * 16 + (lane & 3) * 2;
    float v[4];
    #pragma unroll
    for (int j = 0; j < 4; j++) {
        int k = k0 + (j >> 1) * 8 + (j & 1);
        float val;
        if (layer == 1) {
            if (k < 194)       val = W[k * HID + n];
            else if (k == 194) val = b1[n];
            else               val = 0.f;
        } else {
            val = W[k * HID + n];
        }
        v[j] = val;
    }
    uint4 o;
    split2(v[0], v[1], o.x, o.z);
    split2(v[2], v[3], o.y, o.w);
    g_wfrag[i] = o;
}

__global__ void __launch_bounds__(128) prep_heads_kernel(
    const float* __restrict__ Wvel, const float* __restrict__ bvel,
    const float* __restrict__ Wfh,  const float* __restrict__ bfh,
    const float* __restrict__ Wph,  const float* __restrict__ bph,
    const float* __restrict__ Wmu,  const float* __restrict__ bmu,
    const float* __restrict__ Wstd, const float* __restrict__ bstd)
{
    int k = threadIdx.x;
    g_wh[k * 8 + 0] = Wvel[k * 2 + 0];
    g_wh[k * 8 + 1] = Wvel[k * 2 + 1];
    g_wh[k * 8 + 2] = Wfh[k * 2 + 0];
    g_wh[k * 8 + 3] = Wfh[k * 2 + 1];
    g_wh[k * 8 + 4] = Wph[k * 2 + 0];
    g_wh[k * 8 + 5] = Wph[k * 2 + 1];
    g_wh[k * 8 + 6] = Wmu[k];
    g_wh[k * 8 + 7] = Wstd[k];
    if (k < 8) {
        float hb;
        if      (k < 2)  hb = bvel[k];
        else if (k < 4)  hb = bfh[k - 2];
        else if (k < 6)  hb = bph[k - 4];
        else if (k == 6) hb = bmu[0];
        else             hb = bstd[0];
        g_hb[k] = hb;
    }
}

// interleaved group of 4 n-tiles: dep distance 4 on every accumulator
__device__ __forceinline__ void mma_group4(float (*d)[4], const uint32_t* Ah, const uint32_t* Al,
                                           const uint4* p, int ntBase) {
    uint4 B0 = __ldg(p + (ntBase + 0) * 32);
    uint4 B1 = __ldg(p + (ntBase + 1) * 32);
    uint4 B2 = __ldg(p + (ntBase + 2) * 32);
    uint4 B3 = __ldg(p + (ntBase + 3) * 32);
    float* d0 = d[ntBase + 0];
    float* d1 = d[ntBase + 1];
    float* d2 = d[ntBase + 2];
    float* d3 = d[ntBase + 3];
    mma_bf16(d0, Ah, B0.x, B0.y);
    mma_bf16(d1, Ah, B1.x, B1.y);
    mma_bf16(d2, Ah, B2.x, B2.y);
    mma_bf16(d3, Ah, B3.x, B3.y);
    mma_bf16(d0, Al, B0.x, B0.y);
    mma_bf16(d1, Al, B1.x, B1.y);
    mma_bf16(d2, Al, B2.x, B2.y);
    mma_bf16(d3, Al, B3.x, B3.y);
    mma_bf16(d0, Ah, B0.z, B0.w);
    mma_bf16(d1, Ah, B1.z, B1.w);
    mma_bf16(d2, Ah, B2.z, B2.w);
    mma_bf16(d3, Ah, B3.z, B3.w);
}

// ---------------- main kernel ----------------
__global__ void __launch_bounds__(TPB, 3) pinn_main(
    const float* __restrict__ coords, const float* __restrict__ fourierB,
    const float* __restrict__ b2g, const float* __restrict__ b3g,
    float* __restrict__ out)
{
    extern __shared__ __align__(16) unsigned char smem[];
    const uint32_t sb = smem_u32(smem);
    const int tid  = threadIdx.x;
    const int lane = tid & 31;
    const int warp = tid >> 5;        // 0..3, owns rows warp*16..warp*16+15

    float* sb2 = (float*)(smem + SM_B2);
    float* sb3 = (float*)(smem + SM_B3);
    sb2[tid] = b2g[tid];
    sb3[tid] = b3g[tid];

    // ---- feature build: 2 threads per point (64 points) ----
    {
        int p = tid >> 1, role = tid & 1;
        int m = blockIdx.x * PTS + p;
        uint32_t rowOff = SM_A + (uint32_t)p * SA_STRIDE;
        if (role == 0) {
            float cx = coords[m * 3 + 0], cy = coords[m * 3 + 1];
            int b = m >> 13;
            float fx = (cx + 1.f) * 0.5f * 63.f;
            float fy = (cy + 1.f) * 0.5f * 63.f;
            float x0f = floorf(fx), y0f = floorf(fy);
            int x0 = min(max((int)x0f, 0), 63);
            int x1 = max(min((int)x0f + 1, 63), 0);
            int y0 = min(max((int)y0f, 0), 63);
            int y1 = max(min((int)y0f + 1, 63), 0);
            float wa = (x0f + 1.f - fx) * (y0f + 1.f - fy);
            float wb = (x0f + 1.f - fx) * (fy - y0f);
            float wc = (fx - x0f) * (y0f + 1.f - fy);
            float wd = (fx - x0f) * (fy - y0f);
            const float4* p00 = (const float4*)(g_zt + ((((b << 6) + y0) << 6) + x0) * 64);
            const float4* p01 = (const float4*)(g_zt + ((((b << 6) + y1) << 6) + x0) * 64);
            const float4* p10 = (const float4*)(g_zt + ((((b << 6) + y0) << 6) + x1) * 64);
            const float4* p11 = (const float4*)(g_zt + ((((b << 6) + y1) << 6) + x1) * 64);
            #pragma unroll
            for (int g = 0; g < 16; g++) {
                float4 A = p00[g], B = p01[g], C = p10[g], D = p11[g];
                float v0 = wa*A.x + wb*B.x + wc*C.x + wd*D.x;
                float v1 = wa*A.y + wb*B.y + wc*C.y + wd*D.y;
                float v2 = wa*A.z + wb*B.z + wc*C.z + wd*D.z;
                float v3 = wa*A.w + wb*B.w + wc*C.w + wd*D.w;
                uint32_t h0, l0, h1, l1;
                split2(v0, v1, h0, l0);
                split2(v2, v3, h1, l1);
                *(uint32_t*)(smem + rowOff + g * 8)               = h0;
                *(uint32_t*)(smem + rowOff + g * 8 + 4)           = h1;
                *(uint32_t*)(smem + rowOff + SA_HALF + g * 8)     = l0;
                *(uint32_t*)(smem + rowOff + SA_HALF + g * 8 + 4) = l1;
            }
            // tail: cols 192..207 -> (cx,cy), (1,0), zeros
            uint32_t h, l;
            split2(cx, cy, h, l);
            *(uint32_t*)(smem + rowOff + 384)           = h;
            *(uint32_t*)(smem + rowOff + SA_HALF + 384) = l;
            split2(1.f, 0.f, h, l);
            *(uint32_t*)(smem + rowOff + 388)           = h;
            *(uint32_t*)(smem + rowOff + SA_HALF + 388) = l;
            #pragma unroll
            for (int w = 0; w < 6; w++) {
                *(uint32_t*)(smem + rowOff + 392 + w * 4)           = 0;
                *(uint32_t*)(smem + rowOff + SA_HALF + 392 + w * 4) = 0;
            }
        } else {
            float ct = coords[m * 3 + 2];
            const float tscale = 2.0943951023931953f * ct;  // 2*pi/TEMPORAL_MAX * t
            #pragma unroll 8
            for (int f = 0; f < 32; f++) {
                float s0, c0, s1, c1;
                fsincos(fourierB[2 * f]     * tscale, s0, c0);
                fsincos(fourierB[2 * f + 1] * tscale, s1, c1);
                uint32_t hs, ls, hc, lc;
                split2(s0, s1, hs, ls);
                split2(c0, c1, hc, lc);
                *(uint32_t*)(smem + rowOff + 128 + f * 4)           = hs;  // cols 64..127
                *(uint32_t*)(smem + rowOff + SA_HALF + 128 + f * 4) = ls;
                *(uint32_t*)(smem + rowOff + 256 + f * 4)           = hc;  // cols 128..191
                *(uint32_t*)(smem + rowOff + SA_HALF + 256 + f * 4) = lc;
            }
        }
    }
    __syncthreads();   // features + biases ready; after this, warps are independent

    // ldmatrix A address for this warp's 16 rows
    const uint32_t aAddr = sb + SM_A + (uint32_t)(warp * 16 + (lane & 15)) * SA_STRIDE + (lane >> 4) * 16;

    float d[16][4];

    // ================= layer 1 (A from smem) =================
    #pragma unroll
    for (int nt = 0; nt < 16; nt++)
        #pragma unroll
        for (int i = 0; i < 4; i++) d[nt][i] = 0.f;
    {
        const uint4* wf = g_wfrag + WF_L1 + lane;
        #pragma unroll 1
        for (int kt = 0; kt < L1_KT; kt++) {
            uint32_t Ah[4], Al[4];
            ldsm4(Ah, aAddr + kt * 32);
            ldsm4(Al, aAddr + kt * 32 + SA_HALF);
            const uint4* p = wf + kt * 512;
            #pragma unroll
            for (int ng = 0; ng < 4; ng++)
                mma_group4(d, Ah, Al, p, 4 * ng);
        }
    }

    // epilogue 1 -> A2 in registers (bias folded into W1); D-frag == A-frag layout
    uint32_t A2h[8][4], A2l[8][4];
    #pragma unroll
    for (int kt = 0; kt < 8; kt++)
        #pragma unroll
        for (int j = 0; j < 4; j++) {
            int srcnt = 2 * kt + (j >> 1);
            int c = (j & 1) * 2;
            split2(ftanh(d[srcnt][c]), ftanh(d[srcnt][c + 1]), A2h[kt][j], A2l[kt][j]);
        }

    // ================= layer 2 (A in registers) =================
    #pragma unroll
    for (int nt = 0; nt < 16; nt++)
        #pragma unroll
        for (int i = 0; i < 4; i++) d[nt][i] = 0.f;
    {
        const uint4* wf = g_wfrag + WF_L2 + lane;
        #pragma unroll 1
        for (int kt = 0; kt < L23_KT; kt++) {
            const uint4* p = wf + kt * 512;
            #pragma unroll
            for (int ng = 0; ng < 4; ng++)
                mma_group4(d, A2h[kt], A2l[kt], p, 4 * ng);
        }
    }

    // epilogue 2: +b2, tanh -> A3 (reuse A2 arrays)
    #pragma unroll
    for (int kt = 0; kt < 8; kt++)
        #pragma unroll
        for (int j = 0; j < 4; j++) {
            int srcnt = 2 * kt + (j >> 1);
            int c = (j & 1) * 2;
            int col = 8 * srcnt + (lane & 3) * 2;
            float2 bb = *(float2*)(sb2 + col);
            split2(ftanh(d[srcnt][c] + bb.x), ftanh(d[srcnt][c + 1] + bb.y),
                   A2h[kt][j], A2l[kt][j]);
        }

    // ================= layer 3 (A in registers) =================
    #pragma unroll
    for (int nt = 0; nt < 16; nt++)
        #pragma unroll
        for (int i = 0; i < 4; i++) d[nt][i] = 0.f;
    {
        const uint4* wf = g_wfrag + WF_L3 + lane;
        #pragma unroll 1
        for (int kt = 0; kt < L23_KT; kt++) {
            const uint4* p = wf + kt * 512;
            #pragma unroll
            for (int ng = 0; ng < 4; ng++)
                mma_group4(d, A2h[kt], A2l[kt], p, 4 * ng);
        }
    }

    // epilogue 3: +b3, tanh -> fp32 feat in smem (stride 132 floats)
    {
        float* featF = (float*)(smem + SM_A);
        int row0 = warp * 16 + (lane >> 2);
        #pragma unroll
        for (int nt = 0; nt < 16; nt++) {
            int col = 8 * nt + (lane & 3) * 2;
            float2 bb = *(float2*)(sb3 + col);
            *(float2*)(featF + row0 * 132 + col) =
                make_float2(ftanh(d[nt][0] + bb.x), ftanh(d[nt][1] + bb.y));
            *(float2*)(featF + (row0 + 8) * 132 + col) =
                make_float2(ftanh(d[nt][2] + bb.x), ftanh(d[nt][3] + bb.y));
        }
    }
    __syncthreads();

    // ================= heads =================
    {
        const float* featF = (const float*)(smem + SM_A);
        int p = tid >> 1;
        int og = (tid & 1) * 4;
        const float4* wh4 = (const float4*)g_wh;
        float a0 = 0.f, a1 = 0.f, a2 = 0.f, a3 = 0.f;
        #pragma unroll 4
        for (int k = 0; k < HID; k++) {
            float f = featF[p * 132 + k];
            float4 w = __ldg(wh4 + k * 2 + (tid & 1));
            a0 += f * w.x; a1 += f * w.y; a2 += f * w.z; a3 += f * w.w;
        }
        a0 += g_hb[og]; a1 += g_hb[og + 1]; a2 += g_hb[og + 2]; a3 += g_hb[og + 3];
        if (og == 4) {  // output 7 = softplus(.) + MIN_STD
            a3 = fmaxf(a3, 0.f) + log1pf(expf(-fabsf(a3))) + 0.01f;
        }
        int m = blockIdx.x * PTS + p;
        *(float4*)(out + m * 8 + og) = make_float4(a0, a1, a2, a3);
    }
}

// ---------------- host launch ----------------
extern "C" void kernel_launch(void* const* d_in, const int* in_sizes, int n_in,
                              void* d_out, int out_size) {
    const float* coords   = (const float*)d_in[0];
    const float* z_grid   = (const float*)d_in[1];
    const float* fourierB = (const float*)d_in[2];
    const float* W1   = (const float*)d_in[3];
    const float* b1   = (const float*)d_in[4];
    const float* W2   = (const float*)d_in[5];
    const float* b2   = (const float*)d_in[6];
    const float* W3   = (const float*)d_in[7];
    const float* b3   = (const float*)d_in[8];
    const float* Wvel = (const float*)d_in[9];
    const float* bvel = (const float*)d_in[10];
    const float* Wfh  = (const float*)d_in[11];
    const float* bfh  = (const float*)d_in[12];
    const float* Wph  = (const float*)d_in[13];
    const float* bph  = (const float*)d_in[14];
    const float* Wmu  = (const float*)d_in[15];
    const float* bmu  = (const float*)d_in[16];
    const float* Wstd = (const float*)d_in[17];
    const float* bstd = (const float*)d_in[18];
    float* out = (float*)d_out;

    static bool attr_set = false;
    if (!attr_set) {
        cudaFuncSetAttribute(pinn_main, cudaFuncAttributeMaxDynamicSharedMemorySize, SM_TOTAL);
        attr_set = true;
    }

    transpose_z_kernel<<<(16 * 64 * 64 * 64) / 256, 256>>>(z_grid);
    prep_wfrag_kernel<<<(WF_TOTAL + 255) / 256, 256>>>(W1, b1, W2, W3);
    prep_heads_kernel<<<1, 128>>>(Wvel, bvel, Wfh, bfh, Wph, bph, Wmu, bmu, Wstd, bstd);
    pinn_main<<<NBLK, TPB, SM_TOTAL>>>(coords, fourierB, b2, b3, out);
}